// round 7
// baseline (speedup 1.0000x reference)
#include <cuda_runtime.h>
#include <math.h>

#define N 2048
#define K 8
#define FN 16
#define O 32

#define TJ 128   // j-columns per block
#define TI 64    // i-rows per block

// Scratch (allocation-free): __device__ globals
__device__ float g_rinv[N];
__device__ float g_agg[N * K];
__device__ float g_col[N];

// Kernel 1: one block per row. 256 threads x 8 floats (2x float4) = 2048 cols.
// Block r also zeroes g_agg[r*K..r*K+K) and g_col[r].
__global__ void __launch_bounds__(256) k_rowsum(const float* __restrict__ adj) {
    int row = blockIdx.x;
    int tid = threadIdx.x;

    // Zero this row's accumulator scratch
    if (tid < K) g_agg[row * K + tid] = 0.0f;
    else if (tid == K) g_col[row] = 0.0f;

    const float4* r = (const float4*)(adj + (size_t)row * N);  // 512 float4s
    float4 a = __ldg(r + tid);
    float4 b = __ldg(r + tid + 256);
    float s = (a.x + a.y) + (a.z + a.w) + (b.x + b.y) + (b.z + b.w);

    // Warp reduce
    #pragma unroll
    for (int off = 16; off; off >>= 1) s += __shfl_xor_sync(0xFFFFFFFFu, s, off);

    __shared__ float sred[8];
    int wid = tid >> 5, lane = tid & 31;
    if (lane == 0) sred[wid] = s;
    __syncthreads();
    if (wid == 0) {
        float t = (lane < 8) ? sred[lane] : 0.0f;
        #pragma unroll
        for (int off = 4; off; off >>= 1) t += __shfl_xor_sync(0xFFFFFFFFu, t, off);
        if (lane == 0) {
            float inv = 1.0f / t;
            if (!isfinite(inv)) inv = 0.0f;
            g_rinv[row] = inv;
        }
    }
}

// Kernel 2: main accumulation over E (the 128 MiB read).
// Block = (j-tile of TJ cols) x (i-chunk of TI rows). 256 threads.
// Each thread owns a float4 of the contiguous TJ*K=1024-element (j,k) slab.
// E is loaded with __ldcs (streaming / evict-first): it is read exactly once,
// so keeping it out of L2 preserves adj (16 MiB, read twice) as L2-resident.
__global__ void __launch_bounds__(256) k_accum(const float* __restrict__ E,
                                               const float* __restrict__ adj) {
    const int nJB = N / TJ;                 // 16
    int jb = blockIdx.x % nJB;
    int ib = blockIdx.x / nJB;
    int j0 = jb * TJ;
    int i0 = ib * TI;

    int tid = threadIdx.x;                  // 0..255
    int e0  = tid * 4;                      // element in [0, TJ*K)
    int jl  = e0 >> 3;                      // local j (= tid/2), two threads share a j
    int k0  = e0 & 7;                       // 0 or 4

    __shared__ float s_rinv[TI];
    if (tid < TI) s_rinv[tid] = g_rinv[i0 + tid];
    __syncthreads();

    float4 acc = make_float4(0.f, 0.f, 0.f, 0.f);
    float colp = 0.0f;

    const float* Ebase = E + ((size_t)i0 * N + j0) * K + e0;
    const float* Abase = adj + (size_t)i0 * N + j0 + jl;

    #pragma unroll 16
    for (int ii = 0; ii < TI; ++ii) {
        float s = s_rinv[ii] * __ldg(Abase + (size_t)ii * N);
        float4 ev = __ldcs((const float4*)(Ebase + (size_t)ii * N * K));
        acc.x = fmaf(s, ev.x, acc.x);
        acc.y = fmaf(s, ev.y, acc.y);
        acc.z = fmaf(s, ev.z, acc.z);
        acc.w = fmaf(s, ev.w, acc.w);
        if (k0 == 0) colp += s;
    }

    int j = j0 + jl;
    float* ag = &g_agg[j * K + k0];
    atomicAdd(ag + 0, acc.x);
    atomicAdd(ag + 1, acc.y);
    atomicAdd(ag + 2, acc.z);
    atomicAdd(ag + 3, acc.w);
    if (k0 == 0) atomicAdd(&g_col[j], colp);
}

// Kernel 3: epilogue. Warp per output row j, lane = output col o.
// out[j,o] = sum_k agg[j,k]*W[k,o] + col[j] * sum_f nf[j,f]*W[K+f,o]
__global__ void k_epilogue(const float* __restrict__ nf,
                           const float* __restrict__ W,
                           float* __restrict__ out) {
    int gtid = blockIdx.x * blockDim.x + threadIdx.x;
    int j = gtid >> 5;
    int o = gtid & 31;
    if (j >= N) return;

    float r = 0.0f;
    #pragma unroll
    for (int k = 0; k < K; ++k)
        r = fmaf(g_agg[j * K + k], __ldg(&W[k * O + o]), r);

    float nn = 0.0f;
    #pragma unroll
    for (int f = 0; f < FN; ++f)
        nn = fmaf(__ldg(&nf[j * FN + f]), __ldg(&W[(K + f) * O + o]), nn);

    out[j * O + o] = r + g_col[j] * nn;
}

extern "C" void kernel_launch(void* const* d_in, const int* in_sizes, int n_in,
                              void* d_out, int out_size) {
    const float* node_features = (const float*)d_in[0];   // (N, FN)
    const float* edge_feat     = (const float*)d_in[1];   // (N, N, K)
    const float* adj           = (const float*)d_in[2];   // (N, N)
    const float* weight        = (const float*)d_in[3];   // (K+FN, O)
    float* out = (float*)d_out;                           // (N, O)

    // 1) row sums + scratch zero: one block per row
    k_rowsum<<<N, 256>>>(adj);
    // 2) main accumulation: (N/TJ)*(N/TI) = 16*32 = 512 blocks
    k_accum<<<(N / TJ) * (N / TI), 256>>>(edge_feat, adj);
    // 3) epilogue: 2048 rows * 32 cols / 256 = 256 blocks
    k_epilogue<<<256, 256>>>(node_features, weight, out);
}

// round 8
// speedup vs baseline: 1.2319x; 1.2319x over previous
#include <cuda_runtime.h>
#include <math.h>

#define N 2048
#define K 8
#define FN 16
#define O 32

#define TJ 128   // j-columns per block
#define TI 64    // i-rows per block

// Scratch (allocation-free): __device__ globals
__device__ float g_rinv[N];
__device__ float g_agg[N * K];
__device__ float g_col[N];

// Kernel 1: one block per row. 256 threads x 8 floats (2x float4) = 2048 cols.
// Block r also zeroes g_agg[r*K..r*K+K) and g_col[r].
__global__ void __launch_bounds__(256) k_rowsum(const float* __restrict__ adj) {
    int row = blockIdx.x;
    int tid = threadIdx.x;

    // Zero this row's accumulator scratch
    if (tid < K) g_agg[row * K + tid] = 0.0f;
    else if (tid == K) g_col[row] = 0.0f;

    const float4* r = (const float4*)(adj + (size_t)row * N);  // 512 float4s
    float4 a = __ldg(r + tid);
    float4 b = __ldg(r + tid + 256);
    float s = (a.x + a.y) + (a.z + a.w) + (b.x + b.y) + (b.z + b.w);

    // Warp reduce
    #pragma unroll
    for (int off = 16; off; off >>= 1) s += __shfl_xor_sync(0xFFFFFFFFu, s, off);

    __shared__ float sred[8];
    int wid = tid >> 5, lane = tid & 31;
    if (lane == 0) sred[wid] = s;
    __syncthreads();
    if (wid == 0) {
        float t = (lane < 8) ? sred[lane] : 0.0f;
        #pragma unroll
        for (int off = 4; off; off >>= 1) t += __shfl_xor_sync(0xFFFFFFFFu, t, off);
        if (lane == 0) {
            float inv = 1.0f / t;
            if (!isfinite(inv)) inv = 0.0f;
            g_rinv[row] = inv;
        }
    }
}

// Kernel 2: main accumulation over E (the 128 MiB read).
// Block = (j-tile of TJ cols) x (i-chunk of TI rows). 256 threads.
// Each thread owns a float4 of the contiguous TJ*K=1024-element (j,k) slab.
// E is loaded with __ldcs (streaming / evict-first): it is read exactly once,
// so keeping it out of L2 preserves adj (16 MiB, read twice) as L2-resident.
// unroll 8 deliberately (unroll 16 measured +9us: cross-CTA L1tex-queue
// spread grows with front-batched MLP_p1 per the B300 spread model).
__global__ void __launch_bounds__(256) k_accum(const float* __restrict__ E,
                                               const float* __restrict__ adj) {
    const int nJB = N / TJ;                 // 16
    int jb = blockIdx.x % nJB;
    int ib = blockIdx.x / nJB;
    int j0 = jb * TJ;
    int i0 = ib * TI;

    int tid = threadIdx.x;                  // 0..255
    int e0  = tid * 4;                      // element in [0, TJ*K)
    int jl  = e0 >> 3;                      // local j (= tid/2), two threads share a j
    int k0  = e0 & 7;                       // 0 or 4

    __shared__ float s_rinv[TI];
    if (tid < TI) s_rinv[tid] = g_rinv[i0 + tid];
    __syncthreads();

    float4 acc = make_float4(0.f, 0.f, 0.f, 0.f);
    float colp = 0.0f;

    const float* Ebase = E + ((size_t)i0 * N + j0) * K + e0;
    const float* Abase = adj + (size_t)i0 * N + j0 + jl;

    #pragma unroll 8
    for (int ii = 0; ii < TI; ++ii) {
        float s = s_rinv[ii] * __ldg(Abase + (size_t)ii * N);
        float4 ev = __ldcs((const float4*)(Ebase + (size_t)ii * N * K));
        acc.x = fmaf(s, ev.x, acc.x);
        acc.y = fmaf(s, ev.y, acc.y);
        acc.z = fmaf(s, ev.z, acc.z);
        acc.w = fmaf(s, ev.w, acc.w);
        if (k0 == 0) colp += s;
    }

    int j = j0 + jl;
    float* ag = &g_agg[j * K + k0];
    atomicAdd(ag + 0, acc.x);
    atomicAdd(ag + 1, acc.y);
    atomicAdd(ag + 2, acc.z);
    atomicAdd(ag + 3, acc.w);
    if (k0 == 0) atomicAdd(&g_col[j], colp);
}

// Kernel 3: epilogue. Warp per output row j, lane = output col o.
// out[j,o] = sum_k agg[j,k]*W[k,o] + col[j] * sum_f nf[j,f]*W[K+f,o]
__global__ void k_epilogue(const float* __restrict__ nf,
                           const float* __restrict__ W,
                           float* __restrict__ out) {
    int gtid = blockIdx.x * blockDim.x + threadIdx.x;
    int j = gtid >> 5;
    int o = gtid & 31;
    if (j >= N) return;

    float r = 0.0f;
    #pragma unroll
    for (int k = 0; k < K; ++k)
        r = fmaf(g_agg[j * K + k], __ldg(&W[k * O + o]), r);

    float nn = 0.0f;
    #pragma unroll
    for (int f = 0; f < FN; ++f)
        nn = fmaf(__ldg(&nf[j * FN + f]), __ldg(&W[(K + f) * O + o]), nn);

    out[j * O + o] = r + g_col[j] * nn;
}

extern "C" void kernel_launch(void* const* d_in, const int* in_sizes, int n_in,
                              void* d_out, int out_size) {
    const float* node_features = (const float*)d_in[0];   // (N, FN)
    const float* edge_feat     = (const float*)d_in[1];   // (N, N, K)
    const float* adj           = (const float*)d_in[2];   // (N, N)
    const float* weight        = (const float*)d_in[3];   // (K+FN, O)
    float* out = (float*)d_out;                           // (N, O)

    // 1) row sums + scratch zero: one block per row
    k_rowsum<<<N, 256>>>(adj);
    // 2) main accumulation: (N/TJ)*(N/TI) = 16*32 = 512 blocks
    k_accum<<<(N / TJ) * (N / TI), 256>>>(edge_feat, adj);
    // 3) epilogue: 2048 rows * 32 cols / 256 = 256 blocks
    k_epilogue<<<256, 256>>>(node_features, weight, out);
}